// round 16
// baseline (speedup 1.0000x reference)
#include <cuda_runtime.h>
#include <cuda_fp16.h>
#include <math.h>
#include <stdint.h>

// Problem constants
#define BB   2
#define SS   2048
#define HIDD 1024
#define NHH  16
#define HDD  64
#define MROWS (BB*SS)         // 4096
#define AELEMS (MROWS*HIDD)   // 4194304
#define WELEMS (HIDD*HIDD)    // 1048576

// Scratch (no allocations allowed)
__device__ __half g_hW[4*WELEMS];   // fp16 Wq,Wk,Wv,Wo
__device__ __half g_hQ[AELEMS];     // [B,NH,S,HD] post-RoPE, PRE-SCALED by 0.125*log2e
__device__ __half g_hK[AELEMS];     // [B,NH,S,HD] post-RoPE
__device__ __half g_hV[AELEMS];     // [B,NH,S,HD]
__device__ __half g_hO[AELEMS];     // attention output [B,S,HID]
__device__ float  g_rope[SS*32*2];

#define SCALE2 0.18033688011f       // 0.125 * log2(e)

// ---------------------------------------------------------------------------
__device__ __forceinline__ uint32_t smem_to_u32(const void* p) {
    uint32_t a;
    asm("{ .reg .u64 t; cvta.to.shared.u64 t, %1; cvt.u32.u64 %0, t; }" : "=r"(a) : "l"(p));
    return a;
}
__device__ __forceinline__ void cp_async16(uint32_t dst, const void* src) {
    asm volatile("cp.async.cg.shared.global [%0], [%1], 16;" :: "r"(dst), "l"(src));
}
__device__ __forceinline__ void sts128(uint32_t addr, uint32_t a, uint32_t b,
                                       uint32_t c, uint32_t d) {
    asm volatile("st.shared.v4.b32 [%0], {%1,%2,%3,%4};"
                 :: "r"(addr), "r"(a), "r"(b), "r"(c), "r"(d) : "memory");
}
__device__ __forceinline__ void ldsm_x4(uint32_t* r, uint32_t addr) {
    asm volatile("ldmatrix.sync.aligned.m8n8.x4.shared.b16 {%0,%1,%2,%3}, [%4];"
                 : "=r"(r[0]), "=r"(r[1]), "=r"(r[2]), "=r"(r[3]) : "r"(addr));
}
__device__ __forceinline__ void ldsm_x4_t(uint32_t* r, uint32_t addr) {
    asm volatile("ldmatrix.sync.aligned.m8n8.x4.trans.shared.b16 {%0,%1,%2,%3}, [%4];"
                 : "=r"(r[0]), "=r"(r[1]), "=r"(r[2]), "=r"(r[3]) : "r"(addr));
}
__device__ __forceinline__ uint32_t pack_h2(float lo, float hi) {
    __half2 h = __floats2half2_rn(lo, hi);
    return *(uint32_t*)&h;
}
__device__ __forceinline__ uint32_t h2u(__half2 h) { return *(uint32_t*)&h; }
// m16n8k16 fp16 MMA, fp32 accumulate
__device__ __forceinline__ void mma_f16(float* d, const uint32_t* a, const uint32_t* b) {
    asm volatile(
        "mma.sync.aligned.m16n8k16.row.col.f32.f16.f16.f32 "
        "{%0,%1,%2,%3}, {%4,%5,%6,%7}, {%8,%9}, {%0,%1,%2,%3};"
        : "+f"(d[0]), "+f"(d[1]), "+f"(d[2]), "+f"(d[3])
        : "r"(a[0]), "r"(a[1]), "r"(a[2]), "r"(a[3]), "r"(b[0]), "r"(b[1]));
}

// ---------------------------------------------------------------------------
// Convert WEIGHTS to fp16 + RoPE table. q/k/v are now converted inline in the
// QKV GEMM's A producer path (LDG fp32 -> cvt -> STS fp16), eliminating the
// 72 MB g_hA round-trip.
// ---------------------------------------------------------------------------
#define CVW_UNITS (4 * (WELEMS / 4))          // 1M
#define CVW_BLOCKS (CVW_UNITS / 256)          // 4096
#define ROPE_BLOCKS ((SS * 32 + 255) / 256)   // 256

__global__ void __launch_bounds__(256) convert_kernel(
    const float4* __restrict__ wq, const float4* __restrict__ wk,
    const float4* __restrict__ wv, const float4* __restrict__ wo)
{
    if (blockIdx.x >= CVW_BLOCKS) {   // RoPE table tail
        int idx = (blockIdx.x - CVW_BLOCKS) * 256 + threadIdx.x;
        if (idx < SS * 32) {
            int s = idx >> 5;
            int p = idx & 31;
            const float K2 = -0.20762050593261388f;   // -log2(10000)/64
            float theta = exp2f(K2 * (float)(2 * p));
            float sn, cs;
            sincosf((float)s * theta, &sn, &cs);
            g_rope[idx * 2 + 0] = cs;
            g_rope[idx * 2 + 1] = sn;
        }
        return;
    }
    int i = blockIdx.x * blockDim.x + threadIdx.x;
    int seg = i >> 18;                 // WELEMS/4 = 2^18
    int off = i & ((WELEMS / 4) - 1);
    const float4* src = (seg == 0) ? wq : (seg == 1) ? wk : (seg == 2) ? wv : wo;
    __half* dsth = g_hW + (size_t)seg * WELEMS + (size_t)off * 4;
    float4 x = src[off];
    uint2 o = make_uint2(pack_h2(x.x, x.y), pack_h2(x.z, x.w));
    *(uint2*)dsth = o;
}

// ---------------------------------------------------------------------------
// fp16 mma.sync GEMM: 128x128 CTA tile, BK=32, 512 threads / 16 warps,
// warp tile 32x32, 4-stage pipeline, fp32 accumulate.
// QKV=1: A produced by LDG.128(fp32) -> cvt.f16x2 -> STS.128 (smem image and
//        fragment path identical to the cp.async version; conversion uses the
//        same __floats2half2_rn -> bit-identical results). LDG for stage s+4
//        register-prefetched at iteration s. B via cp.async from g_hW.
// QKV=0: A = g_hO via cp.async (unchanged); W = Wo; fp32 write to C.
// ---------------------------------------------------------------------------
#define RPG 40
#define GSTAGE_BYTES (128 * RPG * 2)          // 10240
#define GEMM_SMEM_BYTES (8 * GSTAGE_BYTES)    // 81920

template<int QKV>
__global__ void __launch_bounds__(512, 2) tc_gemm4(float* __restrict__ C,
                                                   const float* __restrict__ Aq,
                                                   const float* __restrict__ Ak,
                                                   const float* __restrict__ Av)
{
    extern __shared__ char smraw[];
    int z = QKV ? blockIdx.z : 3;
    const float* Af = QKV ? ((z == 0) ? Aq : (z == 1) ? Ak : Av) : nullptr;
    const __half* Ah = QKV ? nullptr : g_hO;
    const __half* W = g_hW + (size_t)z * WELEMS;
    const int K = HIDD;

    uint32_t sA = smem_to_u32(smraw);
    uint32_t sB = sA + 4 * GSTAGE_BYTES;

    int tid  = threadIdx.x;
    int wid  = tid >> 5;
    int lane = tid & 31;
    int wm   = wid & 3;
    int wn   = wid >> 2;
    int rowBase = blockIdx.y * 128;
    int colBase = blockIdx.x * 128;

    int lrow = lane & 7;
    int lmat = lane >> 3;
    uint32_t aOff[2];
#pragma unroll
    for (int mt = 0; mt < 2; mt++) {
        int r = wm * 32 + mt * 16 + (lmat & 1) * 8 + lrow;
        aOff[mt] = (uint32_t)(r * RPG * 2) + (uint32_t)(lmat >> 1) * 16;
    }
    uint32_t bOff[2];
#pragma unroll
    for (int j = 0; j < 2; j++) {
        int r = wn * 32 + j * 16 + (lmat >> 1) * 8 + lrow;
        bOff[j] = (uint32_t)(r * RPG * 2) + (uint32_t)(lmat & 1) * 16;
    }

    float acc[2][4][4];
#pragma unroll
    for (int mt = 0; mt < 2; mt++)
#pragma unroll
        for (int nt = 0; nt < 4; nt++)
#pragma unroll
            for (int e = 0; e < 4; e++) acc[mt][nt][e] = 0.f;

    const int NS = K / 32;

    int gRow = tid >> 2, chk = tid & 3;
    uint32_t sDoffBase = (uint32_t)(gRow * RPG * 2 + chk * 16);
    // fp32 A source for this thread (QKV=1): 8 consecutive floats per stage
    const float* aSrc = QKV ? (Af + (size_t)(rowBase + gRow) * K + chk * 8) : nullptr;
    float4 aPre0, aPre1;   // prefetched fp32 A for the next STS

    // ---- prologue: stages 0,1,2 ----
#pragma unroll
    for (int ps = 0; ps < 3; ps++) {
        int k0 = ps * 32;
        uint32_t bo = (uint32_t)ps * GSTAGE_BYTES;
        if (QKV) {
            float4 p0 = *(const float4*)(aSrc + k0);
            float4 p1 = *(const float4*)(aSrc + k0 + 4);
            sts128(sA + bo + sDoffBase,
                   pack_h2(p0.x, p0.y), pack_h2(p0.z, p0.w),
                   pack_h2(p1.x, p1.y), pack_h2(p1.z, p1.w));
        } else {
            cp_async16(sA + bo + sDoffBase, &Ah[(size_t)(rowBase + gRow) * K + k0 + chk * 8]);
        }
        cp_async16(sB + bo + sDoffBase, &W[(size_t)(colBase + gRow) * K + k0 + chk * 8]);
        asm volatile("cp.async.commit_group;");
    }
    if (QKV) {   // prefetch fp32 A for stage 3
        aPre0 = *(const float4*)(aSrc + 3 * 32);
        aPre1 = *(const float4*)(aSrc + 3 * 32 + 4);
    }

    for (int s = 0; s < NS; s++) {
        if (s < NS - 2)      asm volatile("cp.async.wait_group 2;");
        else if (s < NS - 1) asm volatile("cp.async.wait_group 1;");
        else                 asm volatile("cp.async.wait_group 0;");
        __syncthreads();

        if (s + 3 < NS) {
            int k0 = (s + 3) * 32;
            uint32_t bo = (uint32_t)((s + 3) & 3) * GSTAGE_BYTES;
            if (QKV) {
                sts128(sA + bo + sDoffBase,
                       pack_h2(aPre0.x, aPre0.y), pack_h2(aPre0.z, aPre0.w),
                       pack_h2(aPre1.x, aPre1.y), pack_h2(aPre1.z, aPre1.w));
                if (s + 4 < NS) {
                    aPre0 = *(const float4*)(aSrc + (s + 4) * 32);
                    aPre1 = *(const float4*)(aSrc + (s + 4) * 32 + 4);
                }
            } else {
                cp_async16(sA + bo + sDoffBase, &Ah[(size_t)(rowBase + gRow) * K + k0 + chk * 8]);
            }
            cp_async16(sB + bo + sDoffBase, &W[(size_t)(colBase + gRow) * K + k0 + chk * 8]);
            asm volatile("cp.async.commit_group;");
        }

        uint32_t aBase = sA + (uint32_t)(s & 3) * GSTAGE_BYTES;
        uint32_t bBase = sB + (uint32_t)(s & 3) * GSTAGE_BYTES;
#pragma unroll
        for (int ks = 0; ks < 2; ks++) {
            uint32_t afr[2][4];
#pragma unroll
            for (int mt = 0; mt < 2; mt++)
                ldsm_x4(afr[mt], aBase + aOff[mt] + ks * 32);
            uint32_t bfr[2][4];
#pragma unroll
            for (int j = 0; j < 2; j++)
                ldsm_x4(bfr[j], bBase + bOff[j] + ks * 32);
#pragma unroll
            for (int mt = 0; mt < 2; mt++) {
#pragma unroll
                for (int j = 0; j < 2; j++) {
                    mma_f16(acc[mt][2 * j + 0], afr[mt], &bfr[j][0]);
                    mma_f16(acc[mt][2 * j + 1], afr[mt], &bfr[j][2]);
                }
            }
        }
    }

    int qrow = lane >> 2;
    int qcol = 2 * (lane & 3);
#pragma unroll
    for (int mt = 0; mt < 2; mt++) {
#pragma unroll
        for (int nt = 0; nt < 4; nt++) {
            int c0 = colBase + wn * 32 + nt * 8 + qcol;
            int r0 = rowBase + wm * 32 + mt * 16 + qrow;
#pragma unroll
            for (int half = 0; half < 2; half++) {
                int r = r0 + half * 8;
                float x0 = acc[mt][nt][half * 2 + 0];
                float x1 = acc[mt][nt][half * 2 + 1];
                if (!QKV) {
                    *(float2*)&C[(size_t)r * HIDD + c0] = make_float2(x0, x1);
                } else {
                    int b = r >> 11;
                    int sq = r & (SS - 1);
                    int h  = c0 >> 6;
                    int d0 = c0 & 63;
                    uint32_t o;
                    if (z < 2) {
                        int p = d0 >> 1;
                        float2 rp = *(const float2*)&g_rope[(sq * 32 + p) * 2];
                        if (z == 0) { rp.x *= SCALE2; rp.y *= SCALE2; }
                        o = pack_h2(x0 * rp.x - x1 * rp.y, x1 * rp.x + x0 * rp.y);
                    } else {
                        o = pack_h2(x0, x1);
                    }
                    __half* dstbase = (z == 0) ? g_hQ : (z == 1) ? g_hK : g_hV;
                    *(uint32_t*)&dstbase[((size_t)(b * NHH + h) * SS + sq) * HDD + d0] = o;
                }
            }
        }
    }
}

// ---------------------------------------------------------------------------
// fp16 flash attention (exact R15 version): KV macro-tile 128, per-warp causal
// skip + narrow diagonal path, max-free base-2 softmax, P in registers.
// ---------------------------------------------------------------------------
#define RPA 72
#define ATILE128_BYTES (128 * RPA * 2)        // 18432
#define ATT_SMEM_BYTES (4 * ATILE128_BYTES)   // 73728

__global__ void __launch_bounds__(256, 2) attn_tc() {
    extern __shared__ char smraw[];
    uint32_t ksB = smem_to_u32(smraw);                 // Ks[2] (128-row tiles)
    uint32_t vsB = ksB + 2 * ATILE128_BYTES;           // Vs[2]

    int tid = threadIdx.x;
    int wid = tid >> 5;
    int lane = tid & 31;
    int lr = lane >> 2, lc = lane & 3;
    int lrow = lane & 7, lmat = lane >> 3;
    int qt = gridDim.x - 1 - blockIdx.x;   // heavy tiles first
    int bh = blockIdx.y;
    int qbase = qt * 128;
    int q0 = qbase + wid * 16;

    const __half* Qg = g_hQ + (size_t)bh * SS * HDD;   // pre-scaled by SCALE2
    const __half* Kg = g_hK + (size_t)bh * SS * HDD;
    const __half* Vg = g_hV + (size_t)bh * SS * HDD;

    uint32_t qf[4][4];
#pragma unroll
    for (int ks = 0; ks < 4; ks++) {
        qf[ks][0] = *(const uint32_t*)&Qg[(size_t)(q0 + lr)     * HDD + ks * 16 + 2 * lc];
        qf[ks][1] = *(const uint32_t*)&Qg[(size_t)(q0 + 8 + lr) * HDD + ks * 16 + 2 * lc];
        qf[ks][2] = *(const uint32_t*)&Qg[(size_t)(q0 + lr)     * HDD + ks * 16 + 8 + 2 * lc];
        qf[ks][3] = *(const uint32_t*)&Qg[(size_t)(q0 + 8 + lr) * HDD + ks * 16 + 8 + 2 * lc];
    }

    uint32_t kOff[4];
#pragma unroll
    for (int j = 0; j < 4; j++) {
        int r = j * 16 + (lmat >> 1) * 8 + lrow;
        kOff[j] = (uint32_t)(r * RPA * 2) + (uint32_t)(lmat & 1) * 16;
    }
    uint32_t vOff[4];
#pragma unroll
    for (int j = 0; j < 4; j++) {
        int r = (lmat & 1) * 8 + lrow;
        vOff[j] = (uint32_t)(r * RPA * 2) + (uint32_t)(j * 32 + (lmat >> 1) * 16);
    }

    int crow = tid >> 3;
    int cchk = tid & 7;
    uint32_t sOff = (uint32_t)(crow * RPA * 2 + cchk * 16);

    float oacc[8][4];
#pragma unroll
    for (int nt = 0; nt < 8; nt++)
#pragma unroll
        for (int e = 0; e < 4; e++) oacc[nt][e] = 0.f;
    float l_i[2] = {0.f, 0.f};

    int nkv = qt + 1;   // 128-wide kv tiles

    {   // prologue: stage 128-row tile 0
#pragma unroll
        for (int rep = 0; rep < 4; rep++) {
            int r = crow + rep * 32;
            uint32_t d = sOff + (uint32_t)(rep * 32 * RPA * 2);
            cp_async16(ksB + d, &Kg[(size_t)r * HDD + cchk * 8]);
            cp_async16(vsB + d, &Vg[(size_t)r * HDD + cchk * 8]);
        }
        asm volatile("cp.async.commit_group;");
    }

    for (int kb = 0; kb < nkv; kb++) {
        int buf = kb & 1;
        asm volatile("cp.async.wait_group 0;");
        __syncthreads();

        if (kb + 1 < nkv) {
            int nbase = (kb + 1) * 128;
            uint32_t bo = (uint32_t)((buf ^ 1) * ATILE128_BYTES);
#pragma unroll
            for (int rep = 0; rep < 4; rep++) {
                int r = crow + rep * 32;
                uint32_t d = bo + sOff + (uint32_t)(rep * 32 * RPA * 2);
                cp_async16(ksB + d, &Kg[(size_t)(nbase + r) * HDD + cchk * 8]);
                cp_async16(vsB + d, &Vg[(size_t)(nbase + r) * HDD + cchk * 8]);
            }
            asm volatile("cp.async.commit_group;");
        }

        uint32_t kBase = ksB + (uint32_t)(buf * ATILE128_BYTES);
        uint32_t vBase = vsB + (uint32_t)(buf * ATILE128_BYTES);

#pragma unroll
        for (int half = 0; half < 2; half++) {
            int kvbase = kb * 128 + half * 64;
            if (q0 + 15 < kvbase) continue;   // fully-masked half for this warp
            uint32_t kB2 = kBase + (uint32_t)(half * 64 * RPA * 2);
            uint32_t vB2 = vBase + (uint32_t)(half * 64 * RPA * 2);
            bool partial = (kvbase + 63 > q0);
            bool narrow  = partial && (q0 <= kvbase + 16);

            if (narrow) {
                // ---- Narrow path: nt 0..3 only (cols kvbase..kvbase+31) ----
                float sc[4][4];
#pragma unroll
                for (int nt = 0; nt < 4; nt++)
#pragma unroll
                    for (int e = 0; e < 4; e++) sc[nt][e] = 0.f;
#pragma unroll
                for (int ks = 0; ks < 4; ks++) {
                    uint32_t bfr[2][4];
#pragma unroll
                    for (int j = 0; j < 2; j++)
                        ldsm_x4(bfr[j], kB2 + kOff[j] + ks * 32);
#pragma unroll
                    for (int j = 0; j < 2; j++) {
                        mma_f16(sc[2 * j + 0], qf[ks], &bfr[j][0]);
                        mma_f16(sc[2 * j + 1], qf[ks], &bfr[j][2]);
                    }
                }
#pragma unroll
                for (int h = 0; h < 2; h++) {
                    int qrr = q0 + lr + h * 8;
#pragma unroll
                    for (int nt = 0; nt < 4; nt++)
#pragma unroll
                        for (int e = 0; e < 2; e++)
                            if (kvbase + nt * 8 + 2 * lc + e > qrr)
                                sc[nt][2 * h + e] = -1e30f;
                }
                __half2 pe[2][4];
#pragma unroll
                for (int h = 0; h < 2; h++) {
#pragma unroll
                    for (int nt = 0; nt < 4; nt++)
                        pe[h][nt] = h2exp2(__floats2half2_rn(sc[nt][2 * h], sc[nt][2 * h + 1]));
                    __half2 s0 = __hadd2(pe[h][0], pe[h][1]);
                    __half2 s1 = __hadd2(pe[h][2], pe[h][3]);
                    __half2 st = __hadd2(s0, s1);
                    l_i[h] += __low2float(st) + __high2float(st);
                }
#pragma unroll
                for (int kc = 0; kc < 2; kc++) {
                    uint32_t pa[4];
                    pa[0] = h2u(pe[0][2 * kc]);
                    pa[1] = h2u(pe[1][2 * kc]);
                    pa[2] = h2u(pe[0][2 * kc + 1]);
                    pa[3] = h2u(pe[1][2 * kc + 1]);
                    uint32_t vfr[4][4];
#pragma unroll
                    for (int j = 0; j < 4; j++)
                        ldsm_x4_t(vfr[j], vB2 + vOff[j] + (uint32_t)(kc * 16 * RPA * 2));
#pragma unroll
                    for (int j = 0; j < 4; j++) {
                        mma_f16(oacc[2 * j + 0], pa, &vfr[j][0]);
                        mma_f16(oacc[2 * j + 1], pa, &vfr[j][2]);
                    }
                }
            } else {
                // ---- Full path (with mask when partial) ----
                float sc[8][4];
#pragma unroll
                for (int nt = 0; nt < 8; nt++)
#pragma unroll
                    for (int e = 0; e < 4; e++) sc[nt][e] = 0.f;
#pragma unroll
                for (int ks = 0; ks < 4; ks++) {
                    uint32_t bfr[4][4];
#pragma unroll
                    for (int j = 0; j < 4; j++)
                        ldsm_x4(bfr[j], kB2 + kOff[j] + ks * 32);
#pragma unroll
                    for (int j = 0; j < 4; j++) {
                        mma_f16(sc[2 * j + 0], qf[ks], &bfr[j][0]);
                        mma_f16(sc[2 * j + 1], qf[ks], &bfr[j][2]);
                    }
                }
                if (partial) {
#pragma unroll
                    for (int h = 0; h < 2; h++) {
                        int qrr = q0 + lr + h * 8;
#pragma unroll
                        for (int nt = 0; nt < 8; nt++)
#pragma unroll
                            for (int e = 0; e < 2; e++)
                                if (kvbase + nt * 8 + 2 * lc + e > qrr)
                                    sc[nt][2 * h + e] = -1e30f;
                    }
                }
                __half2 pe[2][8];
#pragma unroll
                for (int h = 0; h < 2; h++) {
#pragma unroll
                    for (int nt = 0; nt < 8; nt++)
                        pe[h][nt] = h2exp2(__floats2half2_rn(sc[nt][2 * h], sc[nt][2 * h + 1]));
                    __half2 s0 = __hadd2(pe[h][0], pe[h][1]);
                    __half2 s1 = __hadd2(pe[h][2], pe[h][3]);
                    __half2 s2 = __hadd2(pe[h][4], pe[h][5]);
                    __half2 s3 = __hadd2(pe[h][6], pe[h][7]);
                    __half2 st = __hadd2(__hadd2(s0, s1), __hadd2(s2, s3));
                    l_i[h] += __low2float(st) + __high2float(st);
                }
#pragma unroll
                for (int kc = 0; kc < 4; kc++) {
                    uint32_t pa[4];
                    pa[0] = h2u(pe[0][2 * kc]);
                    pa[1] = h2u(pe[1][2 * kc]);
                    pa[2] = h2u(pe[0][2 * kc + 1]);
                    pa[3] = h2u(pe[1][2 * kc + 1]);
                    uint32_t vfr[4][4];
#pragma unroll
                    for (int j = 0; j < 4; j++)
                        ldsm_x4_t(vfr[j], vB2 + vOff[j] + (uint32_t)(kc * 16 * RPA * 2));
#pragma unroll
                    for (int j = 0; j < 4; j++) {
                        mma_f16(oacc[2 * j + 0], pa, &vfr[j][0]);
                        mma_f16(oacc[2 * j + 1], pa, &vfr[j][2]);
                    }
                }
            }
        }
    }

    int b = bh >> 4;
    int hh = bh & 15;
#pragma unroll
    for (int h = 0; h < 2; h++) {
        float l = l_i[h];
        l += __shfl_xor_sync(0xffffffffu, l, 1);
        l += __shfl_xor_sync(0xffffffffu, l, 2);
        float inv = 1.0f / l;
        int s = q0 + lr + h * 8;
        __half* orow = g_hO + ((size_t)(b * SS + s)) * HIDD + hh * HDD;
#pragma unroll
        for (int nt = 0; nt < 8; nt++) {
            *(uint32_t*)&orow[nt * 8 + 2 * lc] =
                pack_h2(oacc[nt][2 * h + 0] * inv, oacc[nt][2 * h + 1] * inv);
        }
    }
}

// ---------------------------------------------------------------------------
extern "C" void kernel_launch(void* const* d_in, const int* in_sizes, int n_in,
                              void* d_out, int out_size)
{
    (void)in_sizes; (void)n_in; (void)out_size;
    const float* q  = (const float*)d_in[0];
    const float* k  = (const float*)d_in[1];
    const float* v  = (const float*)d_in[2];
    const float4* Wq = (const float4*)d_in[4];
    const float4* Wk = (const float4*)d_in[5];
    const float4* Wv = (const float4*)d_in[6];
    const float4* Wo = (const float4*)d_in[7];
    float* out = (float*)d_out;

    cudaFuncSetAttribute(tc_gemm4<0>, cudaFuncAttributeMaxDynamicSharedMemorySize, GEMM_SMEM_BYTES);
    cudaFuncSetAttribute(tc_gemm4<1>, cudaFuncAttributeMaxDynamicSharedMemorySize, GEMM_SMEM_BYTES);
    cudaFuncSetAttribute(attn_tc,    cudaFuncAttributeMaxDynamicSharedMemorySize, ATT_SMEM_BYTES);

    convert_kernel<<<CVW_BLOCKS + ROPE_BLOCKS, 256>>>(Wq, Wk, Wv, Wo);

    tc_gemm4<1><<<dim3(HIDD / 128, MROWS / 128, 3), 512, GEMM_SMEM_BYTES>>>(nullptr, q, k, v);

    attn_tc<<<dim3(SS / 128, BB * NHH), 256, ATT_SMEM_BYTES>>>();

    tc_gemm4<0><<<dim3(HIDD / 128, MROWS / 128, 1), 512, GEMM_SMEM_BYTES>>>(out, nullptr, nullptr, nullptr);
}